// round 12
// baseline (speedup 1.0000x reference)
#include <cuda_runtime.h>
#include <math.h>

#define HID   128
#define NH    8
#define NLAY  3
#define NG    64
#define NCLS  3
#define NMAX  50000
#define EMAX  800000

// ------------------------- scratch (static device globals) -------------------------
__device__ float g_h   [(size_t)NMAX * HID];
__device__ float g_agg [(size_t)NMAX * NH * HID];
__device__ float g_as  [(size_t)NMAX * NH];
__device__ float g_ad  [(size_t)NMAX * NH];
__device__ float g_gi  [(size_t)NMAX * 3 * HID];
__device__ float g_gh  [(size_t)NMAX * 3 * HID];
__device__ float g_sums[NG * HID];
__device__ float g_cnt [NG];
__device__ float g_pool[NG * HID];
__device__ float g_us  [NLAY * HID * NH];
__device__ float g_ud  [NLAY * HID * NH];
__device__ float g_wst [NLAY * NH * HID * HID];
// tf32-rounded operand copies
__device__ float g_xr  [(size_t)NMAX * HID];
__device__ float g_memr[(size_t)NMAX * HID];
__device__ float g_encwr[HID * HID];
__device__ float g_wihr[3 * HID * HID];
__device__ float g_whhr[3 * HID * HID];
// CSR
__device__ int   g_deg   [NMAX];
__device__ int   g_rowptr[NMAX + 1];
__device__ int   g_cursor[NMAX];
__device__ int   g_colsrc[EMAX + NMAX];

__device__ __forceinline__ unsigned f2tf32(float f) {
    unsigned r;
    asm("cvt.rna.tf32.f32 %0, %1;" : "=r"(r) : "f"(f));
    return r;
}
__device__ __forceinline__ float rtf(float f) { return __uint_as_float(f2tf32(f)); }

__global__ void zero_kernel(unsigned* p, size_t cnt) {
    size_t i = (size_t)blockIdx.x * blockDim.x + threadIdx.x;
    if (i < cnt) p[i] = 0u;
}

__global__ void round_copy2_kernel(const float* __restrict__ s0, float* __restrict__ d0,
                                   const float* __restrict__ s1, float* __restrict__ d1, size_t cnt) {
    size_t i = (size_t)blockIdx.x * blockDim.x + threadIdx.x;
    if (i >= cnt) return;
    if (blockIdx.y == 0) d0[i] = rtf(s0[i]);
    else                 d1[i] = rtf(s1[i]);
}

__global__ void round_copy_kernel(const float* __restrict__ src, float* __restrict__ dst, size_t cnt) {
    size_t i = (size_t)blockIdx.x * blockDim.x + threadIdx.x;
    if (i < cnt) dst[i] = rtf(src[i]);
}

// ------------------------- CSR build -------------------------
__global__ void hist_kernel(const int* __restrict__ ei, int* __restrict__ deg, int E, int n) {
    int i = blockIdx.x * blockDim.x + threadIdx.x;
    int Etot = E + n;
    if (i >= Etot) return;
    int dst = (i < E) ? ei[(size_t)E + i] : (i - E);
    atomicAdd(&deg[dst], 1);
}

__global__ void scan_kernel(const int* __restrict__ deg, int* __restrict__ rowptr,
                            int* __restrict__ cursor, int n)
{
    __shared__ int part[1024];
    const int t = threadIdx.x;
    const int chunk = (n + 1023) / 1024;
    const int beg = t * chunk;
    const int end = min(beg + chunk, n);
    int s = 0;
    for (int i = beg; i < end; i++) s += deg[i];
    part[t] = s;
    __syncthreads();
    for (int off = 1; off < 1024; off <<= 1) {
        int v = 0;
        if (t >= off) v = part[t - off];
        __syncthreads();
        if (t >= off) part[t] += v;
        __syncthreads();
    }
    int run = (t == 0) ? 0 : part[t - 1];
    for (int i = beg; i < end; i++) {
        rowptr[i] = run; cursor[i] = run;
        run += deg[i];
    }
    if (end == n && beg < n) rowptr[n] = run;
}

__global__ void scatter_kernel(const int* __restrict__ ei, int* __restrict__ cursor,
                               int* __restrict__ colsrc, int E, int n)
{
    int i = blockIdx.x * blockDim.x + threadIdx.x;
    int Etot = E + n;
    if (i >= Etot) return;
    int src, dst;
    if (i < E) { src = ei[i]; dst = ei[(size_t)E + i]; }
    else       { src = dst = i - E; }
    int pos = atomicAdd(&cursor[dst], 1);
    colsrc[pos] = src;
}

// ------------------------- tf32 GEMM: cp.async double-buffered, BK=16 -------------------------
#define BK      16
#define APITCH  20
#define BKNP    136
#define A_STG   (128 * APITCH)
#define B_STG   2560

__device__ __forceinline__ void cpasync16(unsigned dst, const float* src, int srcsize) {
    asm volatile("cp.async.ca.shared.global [%0], [%1], 16, %2;"
                 :: "r"(dst), "l"(src), "r"(srcsize));
}

template <bool TRANSB>
__device__ __forceinline__
void gemm_body(const float* __restrict__ A, const float* __restrict__ B,
               const float* __restrict__ bias, float* __restrict__ C,
               int M, int N, int K, int relu, int round_out, float* sm,
               int bmBlk, int bnBlk)
{
    const int bm = bmBlk * 128;
    const int bn = bnBlk * 128;
    const int tid = threadIdx.x;
    const int lane = tid & 31;
    const int warp = tid >> 5;
    const int wm = warp & 3;
    const int wn = warp >> 2;
    const int gid = lane >> 2;
    const int tig = lane & 3;

    const unsigned smb = (unsigned)__cvta_generic_to_shared(sm);

    const int am   = tid >> 1;
    const int ahalf = (tid & 1) * 8;
    const int bk   = tid >> 4;
    const int bseg = (tid & 15) * 8;

    float c[2][8][4];
#pragma unroll
    for (int i = 0; i < 2; i++)
#pragma unroll
        for (int j = 0; j < 8; j++)
#pragma unroll
            for (int k = 0; k < 4; k++) c[i][j][k] = 0.f;

    const int nt = K / BK;

#define ISSUE(T)                                                                 \
    {                                                                            \
        const int _st = (T) & 1;                                                 \
        const int _kt = (T) * BK;                                                \
        {                                                                        \
            const float* gs = A + (size_t)(bm + am) * K + _kt + ahalf;           \
            int vs = (bm + am < M) ? 16 : 0;                                     \
            unsigned d = smb + (unsigned)((_st * A_STG + am * APITCH + ahalf) * 4); \
            cpasync16(d, gs, vs);                                                \
            cpasync16(d + 16, gs + 4, vs);                                       \
        }                                                                        \
        if (!TRANSB) {                                                           \
            const float* gs = B + (size_t)(_kt + bk) * N + bn + bseg;            \
            unsigned d = smb + (unsigned)((2 * A_STG + _st * B_STG + bk * BKNP + bseg) * 4); \
            cpasync16(d, gs, 16);                                                \
            cpasync16(d + 16, gs + 4, 16);                                       \
        } else {                                                                 \
            const float* gs = B + (size_t)(bn + am) * K + _kt + ahalf;           \
            unsigned d = smb + (unsigned)((2 * A_STG + _st * B_STG + am * APITCH + ahalf) * 4); \
            cpasync16(d, gs, 16);                                                \
            cpasync16(d + 16, gs + 4, 16);                                       \
        }                                                                        \
        asm volatile("cp.async.commit_group;");                                  \
    }

    ISSUE(0);

    for (int t = 0; t < nt; t++) {
        const bool more = (t + 1) < nt;
        if (more) ISSUE(t + 1);
        if (more) asm volatile("cp.async.wait_group 1;");
        else      asm volatile("cp.async.wait_group 0;");
        __syncthreads();

        const int st = t & 1;
        const unsigned* Af = (const unsigned*)(sm + st * A_STG);
        const unsigned* Bf = (const unsigned*)(sm + 2 * A_STG + st * B_STG);

#pragma unroll
        for (int ks = 0; ks < BK; ks += 8) {
            unsigned a[2][4], b[8][2];
#pragma unroll
            for (int i = 0; i < 2; i++) {
                int r0 = wm * 32 + i * 16;
                a[i][0] = Af[(r0 + gid) * APITCH + ks + tig];
                a[i][1] = Af[(r0 + gid + 8) * APITCH + ks + tig];
                a[i][2] = Af[(r0 + gid) * APITCH + ks + tig + 4];
                a[i][3] = Af[(r0 + gid + 8) * APITCH + ks + tig + 4];
            }
#pragma unroll
            for (int j = 0; j < 8; j++) {
                int c0 = wn * 64 + j * 8;
                if (!TRANSB) {
                    b[j][0] = Bf[(ks + tig) * BKNP + c0 + gid];
                    b[j][1] = Bf[(ks + tig + 4) * BKNP + c0 + gid];
                } else {
                    b[j][0] = Bf[(c0 + gid) * APITCH + ks + tig];
                    b[j][1] = Bf[(c0 + gid) * APITCH + ks + tig + 4];
                }
            }
#pragma unroll
            for (int i = 0; i < 2; i++)
#pragma unroll
                for (int j = 0; j < 8; j++) {
                    asm volatile(
                        "mma.sync.aligned.m16n8k8.row.col.f32.tf32.tf32.f32 "
                        "{%0,%1,%2,%3}, {%4,%5,%6,%7}, {%8,%9}, {%0,%1,%2,%3};"
                        : "+f"(c[i][j][0]), "+f"(c[i][j][1]), "+f"(c[i][j][2]), "+f"(c[i][j][3])
                        : "r"(a[i][0]), "r"(a[i][1]), "r"(a[i][2]), "r"(a[i][3]),
                          "r"(b[j][0]), "r"(b[j][1]));
                }
        }
        __syncthreads();
    }
#undef ISSUE

#pragma unroll
    for (int i = 0; i < 2; i++) {
        int row0 = bm + wm * 32 + i * 16 + gid;
#pragma unroll
        for (int j = 0; j < 8; j++) {
            int col = bn + wn * 64 + j * 8 + tig * 2;
            float b0 = bias ? bias[col] : 0.f;
            float b1 = bias ? bias[col + 1] : 0.f;
            float v0 = c[i][j][0] + b0, v1 = c[i][j][1] + b1;
            float v2 = c[i][j][2] + b0, v3 = c[i][j][3] + b1;
            if (relu) {
                v0 = fmaxf(v0, 0.f); v1 = fmaxf(v1, 0.f);
                v2 = fmaxf(v2, 0.f); v3 = fmaxf(v3, 0.f);
            }
            if (round_out) {
                v0 = rtf(v0); v1 = rtf(v1); v2 = rtf(v2); v3 = rtf(v3);
            }
            if (row0 < M)     *(float2*)&C[(size_t)row0 * N + col]       = make_float2(v0, v1);
            if (row0 + 8 < M) *(float2*)&C[(size_t)(row0 + 8) * N + col] = make_float2(v2, v3);
        }
    }
}

template <bool TRANSB>
__global__ __launch_bounds__(256, 2)
void tf32gemm(const float* __restrict__ A, const float* __restrict__ B,
              const float* __restrict__ bias, float* __restrict__ C,
              int M, int N, int K, int relu, int round_out)
{
    __shared__ float sm[2 * (A_STG + B_STG)];
    gemm_body<TRANSB>(A, B, bias, C, M, N, K, relu, round_out, sm,
                      blockIdx.y, blockIdx.x);
}

__global__ __launch_bounds__(256, 2)
void tf32gemm_dual(const float* __restrict__ A0, const float* __restrict__ B0,
                   const float* __restrict__ bias0, float* __restrict__ C0,
                   const float* __restrict__ A1, const float* __restrict__ B1,
                   const float* __restrict__ bias1, float* __restrict__ C1,
                   int M, int N, int K)
{
    __shared__ float sm[2 * (A_STG + B_STG)];
    if (blockIdx.z == 0)
        gemm_body<true>(A0, B0, bias0, C0, M, N, K, 0, 0, sm, blockIdx.y, blockIdx.x);
    else
        gemm_body<true>(A1, B1, bias1, C1, M, N, K, 0, 0, sm, blockIdx.y, blockIdx.x);
}

// ------------------------- weight preprocessing (all layers in one launch) -------------------------
__global__ void stackW_kernel(const float* __restrict__ gatW, float* __restrict__ wst)
{
    int l = blockIdx.y;
    int i = blockIdx.x * blockDim.x + threadIdx.x;
    if (i >= NH * HID * HID) return;
    const float* W = gatW + (size_t)l * HID * NH * HID;
    int c  = i & (HID - 1);
    int kk = i >> 7;
    int h  = kk >> 7;
    int k  = kk & (HID - 1);
    wst[(size_t)l * NH * HID * HID + i] = rtf(W[(size_t)k * (NH * HID) + h * HID + c]);
}

__global__ void fold_att_kernel(const float* __restrict__ gatW,
                                const float* __restrict__ att_s, const float* __restrict__ att_d,
                                float* __restrict__ us, float* __restrict__ ud)
{
    int l = blockIdx.y;
    int h = blockIdx.x;
    int cidx = threadIdx.x;
    const float* wrow = gatW + (size_t)l * HID * NH * HID + (size_t)cidx * (NH * HID) + h * HID;
    const float* asv = att_s + (size_t)l * NH * HID + h * HID;
    const float* adv = att_d + (size_t)l * NH * HID + h * HID;
    float ss = 0.f, sd = 0.f;
    for (int k = 0; k < HID; k++) {
        float w = wrow[k];
        ss += w * asv[k];
        sd += w * adv[k];
    }
    us[(size_t)l * HID * NH + cidx * NH + h] = ss;
    ud[(size_t)l * HID * NH + cidx * NH + h] = sd;
}

// ------------------------- alphas from h (folded) -------------------------
__global__ void alpha2_kernel(const float* __restrict__ hmat,
                              const float* __restrict__ us, const float* __restrict__ ud,
                              float* __restrict__ as_, float* __restrict__ ad_, int n)
{
    __shared__ float su[HID * NH], sd[HID * NH];
    for (int i = threadIdx.x; i < HID * NH; i += blockDim.x) {
        su[i] = us[i]; sd[i] = ud[i];
    }
    __syncthreads();
    int node = blockIdx.x * 8 + (threadIdx.x >> 5);
    if (node >= n) return;
    int lane = threadIdx.x & 31;
    float4 hv = *(const float4*)(hmat + (size_t)node * HID + lane * 4);
    float aS[NH], aD[NH];
#pragma unroll
    for (int hd = 0; hd < NH; hd++) {
        int b = (lane * 4) * NH + hd;
        aS[hd] = hv.x * su[b] + hv.y * su[b + NH] + hv.z * su[b + 2 * NH] + hv.w * su[b + 3 * NH];
        aD[hd] = hv.x * sd[b] + hv.y * sd[b + NH] + hv.z * sd[b + 2 * NH] + hv.w * sd[b + 3 * NH];
    }
#pragma unroll
    for (int off = 16; off > 0; off >>= 1) {
#pragma unroll
        for (int hd = 0; hd < NH; hd++) {
            aS[hd] += __shfl_xor_sync(0xffffffffu, aS[hd], off);
            aD[hd] += __shfl_xor_sync(0xffffffffu, aD[hd], off);
        }
    }
    if (lane < 8) {
        as_[(size_t)node * NH + lane] = aS[lane];
        ad_[(size_t)node * NH + lane] = aD[lane];
    }
}

// ------------------------- single-pass fused GAT edge kernel (R7 2-deep pipeline) -------------------------
__device__ __forceinline__ float lrelu(float v) { return (v > 0.f) ? v : 0.2f * v; }

__global__ void gat_fused_kernel(const int* __restrict__ rowptr, const int* __restrict__ colsrc,
                                 const float* __restrict__ as_, const float* __restrict__ ad_,
                                 const float* __restrict__ hmat, float* __restrict__ agg, int n)
{
    int w = (blockIdx.x * blockDim.x + threadIdx.x) >> 5;
    int lane = threadIdx.x & 31;
    if (w >= n) return;
    const int dst = w;
    const int start = rowptr[dst];
    const int end   = rowptr[dst + 1];
    const int hh = lane & 7;

    const float advh = ad_[(size_t)dst * NH + hh];

    float4 acc[8];
#pragma unroll
    for (int h = 0; h < 8; h++) acc[h] = make_float4(0.f, 0.f, 0.f, 0.f);
    float den = 0.f;

    // 2-deep pipeline
    int   s_nx = colsrc[start];
    float c_nx = __expf(lrelu(as_[(size_t)s_nx * NH + hh] + advh));
    float4 h_nx = *(const float4*)(hmat + (size_t)s_nx * HID + lane * 4);

    for (int j = start; j < end; j++) {
        float4 hv = h_nx;
        float  cl = c_nx;
        if (j + 1 < end) {
            s_nx = colsrc[j + 1];
            c_nx = __expf(lrelu(as_[(size_t)s_nx * NH + hh] + advh));
            h_nx = *(const float4*)(hmat + (size_t)s_nx * HID + lane * 4);
        }
        den += cl;
#pragma unroll
        for (int h = 0; h < 8; h++) {
            float cc = __shfl_sync(0xffffffffu, cl, h);
            acc[h].x += cc * hv.x; acc[h].y += cc * hv.y;
            acc[h].z += cc * hv.z; acc[h].w += cc * hv.w;
        }
    }

    float invh = 0.125f / (den + 1e-16f);
    float* ap = agg + (size_t)dst * (NH * HID);
#pragma unroll
    for (int h = 0; h < 8; h++) {
        float iv = __shfl_sync(0xffffffffu, invh, h);
        float4 o = make_float4(rtf(acc[h].x * iv), rtf(acc[h].y * iv),
                               rtf(acc[h].z * iv), rtf(acc[h].w * iv));
        *(float4*)(ap + h * HID + lane * 4) = o;
    }
}

// ------------------------- fused GRU + pooling -------------------------
__global__ void gru_pool_kernel(const float* __restrict__ gi, const float* __restrict__ gh,
                                const float* __restrict__ mem, const int* __restrict__ batch,
                                float* __restrict__ sums, float* __restrict__ cnt, int n)
{
    int i = blockIdx.x * blockDim.x + threadIdx.x;
    if (i >= n * HID) return;
    int node = i >> 7, c = i & (HID - 1);
    size_t base = (size_t)node * (3 * HID);
    float gir = gi[base + c],           ghr = gh[base + c];
    float giz = gi[base + HID + c],     ghz = gh[base + HID + c];
    float gin = gi[base + 2 * HID + c], ghn = gh[base + 2 * HID + c];
    float r = 1.f / (1.f + expf(-(gir + ghr)));
    float z = 1.f / (1.f + expf(-(giz + ghz)));
    float nc = tanhf(gin + r * ghn);
    float mv = mem[i];
    float hn = (1.f - z) * nc + z * mv;
    int g = batch[node];
    atomicAdd(&sums[g * HID + c], hn);
    if (c == 0) atomicAdd(&cnt[g], 1.f);
}

__global__ void pooled_kernel(const float* __restrict__ sums, const float* __restrict__ cnt,
                              float* __restrict__ pooled, float* __restrict__ out_pooled)
{
    int i = blockIdx.x * blockDim.x + threadIdx.x;
    if (i >= NG * HID) return;
    int g = i >> 7;
    float v = sums[i] / fmaxf(cnt[g], 1.f);
    pooled[i] = v;
    out_pooled[i] = v;
}

__global__ void classifier_kernel(const float* __restrict__ pooled,
                                  const float* __restrict__ c1W, const float* __restrict__ c1b,
                                  const float* __restrict__ c2W, const float* __restrict__ c2b,
                                  float* __restrict__ out_logits, float* __restrict__ out_preds)
{
    int g = threadIdx.x;
    if (g >= NG) return;
    const float* p = pooled + g * HID;
    float lg[NCLS];
#pragma unroll
    for (int k = 0; k < NCLS; k++) lg[k] = c2b[k];
    for (int j = 0; j < HID / 2; j++) {
        float s = c1b[j];
        for (int c = 0; c < HID; c++) s += p[c] * c1W[c * (HID / 2) + j];
        s = fmaxf(s, 0.f);
#pragma unroll
        for (int k = 0; k < NCLS; k++) lg[k] += s * c2W[j * NCLS + k];
    }
    float m = fmaxf(lg[0], fmaxf(lg[1], lg[2]));
    float e0 = expf(lg[0] - m), e1 = expf(lg[1] - m), e2 = expf(lg[2] - m);
    float inv = 1.f / (e0 + e1 + e2);
#pragma unroll
    for (int k = 0; k < NCLS; k++) out_logits[g * NCLS + k] = lg[k];
    out_preds[g * NCLS + 0] = e0 * inv;
    out_preds[g * NCLS + 1] = e1 * inv;
    out_preds[g * NCLS + 2] = e2 * inv;
}

// ------------------------- launch -------------------------
extern "C" void kernel_launch(void* const* d_in, const int* in_sizes, int n_in,
                              void* d_out, int out_size)
{
    const float* x      = (const float*)d_in[0];
    const int*   ei     = (const int*)d_in[1];
    const int*   batch  = (const int*)d_in[2];
    const float* memory = (const float*)d_in[3];
    const float* enc_W  = (const float*)d_in[4];
    const float* enc_b  = (const float*)d_in[5];
    const float* gat_W  = (const float*)d_in[6];
    const float* att_s  = (const float*)d_in[7];
    const float* att_d  = (const float*)d_in[8];
    const float* gat_b  = (const float*)d_in[9];
    const float* W_ih   = (const float*)d_in[10];
    const float* W_hh   = (const float*)d_in[11];
    const float* b_ih   = (const float*)d_in[12];
    const float* b_hh   = (const float*)d_in[13];
    const float* c1W    = (const float*)d_in[14];
    const float* c1b    = (const float*)d_in[15];
    const float* c2W    = (const float*)d_in[16];
    const float* c2b    = (const float*)d_in[17];
    float* out = (float*)d_out;

    const int n    = in_sizes[2];
    const int E    = in_sizes[1] / 2;
    const int Etot = E + n;
    const int F    = in_sizes[0] / n;

    float *h, *agg, *as_, *ad_, *gi, *gh, *sums, *cnt, *pooled, *us, *ud, *wst;
    float *xr, *memr, *encwr, *wihr, *whhr;
    int *deg, *rowptr, *cursor, *colsrc;
    cudaGetSymbolAddress((void**)&h, g_h);
    cudaGetSymbolAddress((void**)&agg, g_agg);
    cudaGetSymbolAddress((void**)&as_, g_as);
    cudaGetSymbolAddress((void**)&ad_, g_ad);
    cudaGetSymbolAddress((void**)&gi, g_gi);
    cudaGetSymbolAddress((void**)&gh, g_gh);
    cudaGetSymbolAddress((void**)&sums, g_sums);
    cudaGetSymbolAddress((void**)&cnt, g_cnt);
    cudaGetSymbolAddress((void**)&pooled, g_pool);
    cudaGetSymbolAddress((void**)&us, g_us);
    cudaGetSymbolAddress((void**)&ud, g_ud);
    cudaGetSymbolAddress((void**)&wst, g_wst);
    cudaGetSymbolAddress((void**)&xr, g_xr);
    cudaGetSymbolAddress((void**)&memr, g_memr);
    cudaGetSymbolAddress((void**)&encwr, g_encwr);
    cudaGetSymbolAddress((void**)&wihr, g_wihr);
    cudaGetSymbolAddress((void**)&whhr, g_whhr);
    cudaGetSymbolAddress((void**)&deg, g_deg);
    cudaGetSymbolAddress((void**)&rowptr, g_rowptr);
    cudaGetSymbolAddress((void**)&cursor, g_cursor);
    cudaGetSymbolAddress((void**)&colsrc, g_colsrc);

    const int T = 256;

    // ---- build CSR (dst-sorted) once ----
    zero_kernel<<<(n + T - 1) / T, T>>>((unsigned*)deg, n);
    hist_kernel<<<(Etot + T - 1) / T, T>>>(ei, deg, E, n);
    scan_kernel<<<1, 1024>>>(deg, rowptr, cursor, n);
    scatter_kernel<<<(Etot + T - 1) / T, T>>>(ei, cursor, colsrc, E, n);

    // ---- zero pool accumulators early ----
    zero_kernel<<<(NG * HID + T - 1) / T, T>>>((unsigned*)sums, NG * HID);
    zero_kernel<<<1, NG>>>((unsigned*)cnt, NG);

    // ---- tf32 pre-rounding of all mma operands ----
    {
        dim3 g2((unsigned)(((size_t)n * HID + T - 1) / T), 2);
        round_copy2_kernel<<<g2, T>>>(x, xr, memory, memr, (size_t)n * HID);
    }
    round_copy_kernel<<<(HID * HID + T - 1) / T, T>>>(enc_W, encwr, HID * HID);
    round_copy_kernel<<<(3 * HID * HID + T - 1) / T, T>>>(W_ih, wihr, 3 * HID * HID);
    round_copy_kernel<<<(3 * HID * HID + T - 1) / T, T>>>(W_hh, whhr, 3 * HID * HID);

    stackW_kernel<<<dim3((NH * HID * HID + T - 1) / T, NLAY), T>>>(gat_W, wst);
    fold_att_kernel<<<dim3(NH, NLAY), HID>>>(gat_W, att_s, att_d, us, ud);

    const int MB = (n + 127) / 128;

    // ---- encoder ----
    tf32gemm<false><<<dim3(1, MB), T>>>(xr, encwr, enc_b, h, n, HID, F, 1, 0);

    // ---- GAT layers ----
    for (int l = 0; l < NLAY; l++) {
        alpha2_kernel<<<(n + 7) / 8, T>>>(h, us + (size_t)l * HID * NH,
                                          ud + (size_t)l * HID * NH, as_, ad_, n);
        gat_fused_kernel<<<(int)(((size_t)n * 32 + T - 1) / T), T>>>(
            rowptr, colsrc, as_, ad_, h, agg, n);
        tf32gemm<false><<<dim3(1, MB), T>>>(
            agg, wst + (size_t)l * NH * HID * HID, gat_b + (size_t)l * HID, h,
            n, HID, NH * HID, (l < NLAY - 1) ? 1 : 0, (l == NLAY - 1) ? 1 : 0);
    }

    // ---- GRU (both projections in one launch) ----
    tf32gemm_dual<<<dim3(3 * HID / 128, MB, 2), T>>>(
        h, wihr, b_ih, gi, memr, whhr, b_hh, gh, n, 3 * HID, HID);
    gru_pool_kernel<<<(int)(((size_t)n * HID + T - 1) / T), T>>>(
        gi, gh, memr, batch, sums, cnt, n);

    // ---- pooled + classifier ----
    float* out_logits = out;
    float* out_pooled = out + NG * NCLS;
    float* out_preds  = out + NG * NCLS + NG * HID;
    pooled_kernel<<<(NG * HID + T - 1) / T, T>>>(sums, cnt, pooled, out_pooled);
    classifier_kernel<<<1, NG>>>(pooled, c1W, c1b, c2W, c2b, out_logits, out_preds);
}

// round 15
// speedup vs baseline: 1.0132x; 1.0132x over previous
#include <cuda_runtime.h>
#include <math.h>

#define HID   128
#define NH    8
#define NLAY  3
#define NG    64
#define NCLS  3
#define NMAX  50000
#define EMAX  800000

// ------------------------- scratch (static device globals) -------------------------
__device__ float g_h   [(size_t)NMAX * HID];
__device__ float g_agg [(size_t)NMAX * NH * HID];
__device__ float g_as  [(size_t)NMAX * NH];
__device__ float g_ad  [(size_t)NMAX * NH];
__device__ float g_gi  [(size_t)NMAX * 3 * HID];
__device__ float g_gh  [(size_t)NMAX * 3 * HID];
__device__ float g_sums[NG * HID];
__device__ float g_cnt [NG];
__device__ float g_pool[NG * HID];
__device__ float g_us  [NLAY * HID * NH];
__device__ float g_ud  [NLAY * HID * NH];
__device__ float g_wst [NLAY * NH * HID * HID];
// tf32-rounded operand copies
__device__ float g_xr  [(size_t)NMAX * HID];
__device__ float g_memr[(size_t)NMAX * HID];
__device__ float g_encwr[HID * HID];
__device__ float g_wihr[3 * HID * HID];
__device__ float g_whhr[3 * HID * HID];
// CSR
__device__ int   g_deg   [NMAX];
__device__ int   g_rowptr[NMAX + 1];
__device__ int   g_cursor[NMAX];
__device__ int   g_colsrc[EMAX + NMAX];

__device__ __forceinline__ unsigned f2tf32(float f) {
    unsigned r;
    asm("cvt.rna.tf32.f32 %0, %1;" : "=r"(r) : "f"(f));
    return r;
}
__device__ __forceinline__ float rtf(float f) { return __uint_as_float(f2tf32(f)); }

__global__ void zero_kernel(unsigned* p, size_t cnt) {
    size_t i = (size_t)blockIdx.x * blockDim.x + threadIdx.x;
    if (i < cnt) p[i] = 0u;
}

__global__ void round_copy2_kernel(const float* __restrict__ s0, float* __restrict__ d0,
                                   const float* __restrict__ s1, float* __restrict__ d1, size_t cnt) {
    size_t i = (size_t)blockIdx.x * blockDim.x + threadIdx.x;
    if (i >= cnt) return;
    if (blockIdx.y == 0) d0[i] = rtf(s0[i]);
    else                 d1[i] = rtf(s1[i]);
}

__global__ void round_copy_kernel(const float* __restrict__ src, float* __restrict__ dst, size_t cnt) {
    size_t i = (size_t)blockIdx.x * blockDim.x + threadIdx.x;
    if (i < cnt) dst[i] = rtf(src[i]);
}

// ------------------------- CSR build -------------------------
__global__ void hist_kernel(const int* __restrict__ ei, int* __restrict__ deg, int E, int n) {
    int i = blockIdx.x * blockDim.x + threadIdx.x;
    int Etot = E + n;
    if (i >= Etot) return;
    int dst = (i < E) ? ei[(size_t)E + i] : (i - E);
    atomicAdd(&deg[dst], 1);
}

__global__ void scan_kernel(const int* __restrict__ deg, int* __restrict__ rowptr,
                            int* __restrict__ cursor, int n)
{
    __shared__ int part[1024];
    const int t = threadIdx.x;
    const int chunk = (n + 1023) / 1024;
    const int beg = t * chunk;
    const int end = min(beg + chunk, n);
    int s = 0;
    for (int i = beg; i < end; i++) s += deg[i];
    part[t] = s;
    __syncthreads();
    for (int off = 1; off < 1024; off <<= 1) {
        int v = 0;
        if (t >= off) v = part[t - off];
        __syncthreads();
        if (t >= off) part[t] += v;
        __syncthreads();
    }
    int run = (t == 0) ? 0 : part[t - 1];
    for (int i = beg; i < end; i++) {
        rowptr[i] = run; cursor[i] = run;
        run += deg[i];
    }
    if (end == n && beg < n) rowptr[n] = run;
}

__global__ void scatter_kernel(const int* __restrict__ ei, int* __restrict__ cursor,
                               int* __restrict__ colsrc, int E, int n)
{
    int i = blockIdx.x * blockDim.x + threadIdx.x;
    int Etot = E + n;
    if (i >= Etot) return;
    int src, dst;
    if (i < E) { src = ei[i]; dst = ei[(size_t)E + i]; }
    else       { src = dst = i - E; }
    int pos = atomicAdd(&cursor[dst], 1);
    colsrc[pos] = src;
}

// ------------------------- tf32 GEMM: 3-stage cp.async ring, one sync/tile -------------------------
#define BK      16
#define NSTG    3
#define APITCH  20
#define BKNP    136
#define A_STG   (128 * APITCH)   // 2560 floats
#define B_STG   2560
#define SMEM_GEMM (NSTG * (A_STG + B_STG) * 4)   // 61440 bytes

__device__ __forceinline__ void cpasync16(unsigned dst, const float* src, int srcsize) {
    asm volatile("cp.async.ca.shared.global [%0], [%1], 16, %2;"
                 :: "r"(dst), "l"(src), "r"(srcsize));
}

template <bool TRANSB>
__device__ __forceinline__
void gemm_body(const float* __restrict__ A, const float* __restrict__ B,
               const float* __restrict__ bias, float* __restrict__ C,
               int M, int N, int K, int relu, int round_out, float* sm,
               int bmBlk, int bnBlk)
{
    const int bm = bmBlk * 128;
    const int bn = bnBlk * 128;
    const int tid = threadIdx.x;
    const int lane = tid & 31;
    const int warp = tid >> 5;
    const int wm = warp & 3;
    const int wn = warp >> 2;
    const int gid = lane >> 2;
    const int tig = lane & 3;

    const unsigned smb = (unsigned)__cvta_generic_to_shared(sm);

    const int am    = tid >> 1;
    const int ahalf = (tid & 1) * 8;
    const int bk    = tid >> 4;
    const int bseg  = (tid & 15) * 8;

    float c[2][8][4];
#pragma unroll
    for (int i = 0; i < 2; i++)
#pragma unroll
        for (int j = 0; j < 8; j++)
#pragma unroll
            for (int k = 0; k < 4; k++) c[i][j][k] = 0.f;

    const int nt = K / BK;

#define ISSUE(T)                                                                 \
    {                                                                            \
        const int _st = (T) % NSTG;                                              \
        const int _kt = (T) * BK;                                                \
        {                                                                        \
            const float* gs = A + (size_t)(bm + am) * K + _kt + ahalf;           \
            int vs = (bm + am < M) ? 16 : 0;                                     \
            unsigned d = smb + (unsigned)((_st * A_STG + am * APITCH + ahalf) * 4); \
            cpasync16(d, gs, vs);                                                \
            cpasync16(d + 16, gs + 4, vs);                                       \
        }                                                                        \
        if (!TRANSB) {                                                           \
            const float* gs = B + (size_t)(_kt + bk) * N + bn + bseg;            \
            unsigned d = smb + (unsigned)((NSTG * A_STG + _st * B_STG + bk * BKNP + bseg) * 4); \
            cpasync16(d, gs, 16);                                                \
            cpasync16(d + 16, gs + 4, 16);                                       \
        } else {                                                                 \
            const float* gs = B + (size_t)(bn + am) * K + _kt + ahalf;           \
            unsigned d = smb + (unsigned)((NSTG * A_STG + _st * B_STG + am * APITCH + ahalf) * 4); \
            cpasync16(d, gs, 16);                                                \
            cpasync16(d + 16, gs + 4, 16);                                       \
        }                                                                        \
        asm volatile("cp.async.commit_group;");                                  \
    }

    ISSUE(0);
    if (nt > 1) ISSUE(1);

    for (int t = 0; t < nt; t++) {
        if (t + 1 < nt) asm volatile("cp.async.wait_group 1;");
        else            asm volatile("cp.async.wait_group 0;");
        __syncthreads();

        const int st = t % NSTG;
        const unsigned* Af = (const unsigned*)(sm + st * A_STG);
        const unsigned* Bf = (const unsigned*)(sm + NSTG * A_STG + st * B_STG);

#pragma unroll
        for (int ks = 0; ks < BK; ks += 8) {
            unsigned a[2][4], b[8][2];
#pragma unroll
            for (int i = 0; i < 2; i++) {
                int r0 = wm * 32 + i * 16;
                a[i][0] = Af[(r0 + gid) * APITCH + ks + tig];
                a[i][1] = Af[(r0 + gid + 8) * APITCH + ks + tig];
                a[i][2] = Af[(r0 + gid) * APITCH + ks + tig + 4];
                a[i][3] = Af[(r0 + gid + 8) * APITCH + ks + tig + 4];
            }
#pragma unroll
            for (int j = 0; j < 8; j++) {
                int c0 = wn * 64 + j * 8;
                if (!TRANSB) {
                    b[j][0] = Bf[(ks + tig) * BKNP + c0 + gid];
                    b[j][1] = Bf[(ks + tig + 4) * BKNP + c0 + gid];
                } else {
                    b[j][0] = Bf[(c0 + gid) * APITCH + ks + tig];
                    b[j][1] = Bf[(c0 + gid) * APITCH + ks + tig + 4];
                }
            }
#pragma unroll
            for (int i = 0; i < 2; i++)
#pragma unroll
                for (int j = 0; j < 8; j++) {
                    asm volatile(
                        "mma.sync.aligned.m16n8k8.row.col.f32.tf32.tf32.f32 "
                        "{%0,%1,%2,%3}, {%4,%5,%6,%7}, {%8,%9}, {%0,%1,%2,%3};"
                        : "+f"(c[i][j][0]), "+f"(c[i][j][1]), "+f"(c[i][j][2]), "+f"(c[i][j][3])
                        : "r"(a[i][0]), "r"(a[i][1]), "r"(a[i][2]), "r"(a[i][3]),
                          "r"(b[j][0]), "r"(b[j][1]));
                }
        }

        // issue tile t+2 AFTER compute: the barrier at iteration t+1 protects
        // slot (t+3)%3 == t%3 from being overwritten while still being read.
        if (t + 2 < nt) ISSUE(t + 2);
    }
#undef ISSUE

#pragma unroll
    for (int i = 0; i < 2; i++) {
        int row0 = bm + wm * 32 + i * 16 + gid;
#pragma unroll
        for (int j = 0; j < 8; j++) {
            int col = bn + wn * 64 + j * 8 + tig * 2;
            float b0 = bias ? bias[col] : 0.f;
            float b1 = bias ? bias[col + 1] : 0.f;
            float v0 = c[i][j][0] + b0, v1 = c[i][j][1] + b1;
            float v2 = c[i][j][2] + b0, v3 = c[i][j][3] + b1;
            if (relu) {
                v0 = fmaxf(v0, 0.f); v1 = fmaxf(v1, 0.f);
                v2 = fmaxf(v2, 0.f); v3 = fmaxf(v3, 0.f);
            }
            if (round_out) {
                v0 = rtf(v0); v1 = rtf(v1); v2 = rtf(v2); v3 = rtf(v3);
            }
            if (row0 < M)     *(float2*)&C[(size_t)row0 * N + col]       = make_float2(v0, v1);
            if (row0 + 8 < M) *(float2*)&C[(size_t)(row0 + 8) * N + col] = make_float2(v2, v3);
        }
    }
}

template <bool TRANSB>
__global__ __launch_bounds__(256, 2)
void tf32gemm(const float* __restrict__ A, const float* __restrict__ B,
              const float* __restrict__ bias, float* __restrict__ C,
              int M, int N, int K, int relu, int round_out)
{
    extern __shared__ float sm[];
    gemm_body<TRANSB>(A, B, bias, C, M, N, K, relu, round_out, sm,
                      blockIdx.y, blockIdx.x);
}

__global__ __launch_bounds__(256, 2)
void tf32gemm_dual(const float* __restrict__ A0, const float* __restrict__ B0,
                   const float* __restrict__ bias0, float* __restrict__ C0,
                   const float* __restrict__ A1, const float* __restrict__ B1,
                   const float* __restrict__ bias1, float* __restrict__ C1,
                   int M, int N, int K)
{
    extern __shared__ float sm[];
    if (blockIdx.z == 0)
        gemm_body<true>(A0, B0, bias0, C0, M, N, K, 0, 0, sm, blockIdx.y, blockIdx.x);
    else
        gemm_body<true>(A1, B1, bias1, C1, M, N, K, 0, 0, sm, blockIdx.y, blockIdx.x);
}

// ------------------------- weight preprocessing (all layers in one launch) -------------------------
__global__ void stackW_kernel(const float* __restrict__ gatW, float* __restrict__ wst)
{
    int l = blockIdx.y;
    int i = blockIdx.x * blockDim.x + threadIdx.x;
    if (i >= NH * HID * HID) return;
    const float* W = gatW + (size_t)l * HID * NH * HID;
    int c  = i & (HID - 1);
    int kk = i >> 7;
    int h  = kk >> 7;
    int k  = kk & (HID - 1);
    wst[(size_t)l * NH * HID * HID + i] = rtf(W[(size_t)k * (NH * HID) + h * HID + c]);
}

__global__ void fold_att_kernel(const float* __restrict__ gatW,
                                const float* __restrict__ att_s, const float* __restrict__ att_d,
                                float* __restrict__ us, float* __restrict__ ud)
{
    int l = blockIdx.y;
    int h = blockIdx.x;
    int cidx = threadIdx.x;
    const float* wrow = gatW + (size_t)l * HID * NH * HID + (size_t)cidx * (NH * HID) + h * HID;
    const float* asv = att_s + (size_t)l * NH * HID + h * HID;
    const float* adv = att_d + (size_t)l * NH * HID + h * HID;
    float ss = 0.f, sd = 0.f;
    for (int k = 0; k < HID; k++) {
        float w = wrow[k];
        ss += w * asv[k];
        sd += w * adv[k];
    }
    us[(size_t)l * HID * NH + cidx * NH + h] = ss;
    ud[(size_t)l * HID * NH + cidx * NH + h] = sd;
}

// ------------------------- alphas from h (folded) -------------------------
__global__ void alpha2_kernel(const float* __restrict__ hmat,
                              const float* __restrict__ us, const float* __restrict__ ud,
                              float* __restrict__ as_, float* __restrict__ ad_, int n)
{
    __shared__ float su[HID * NH], sd[HID * NH];
    for (int i = threadIdx.x; i < HID * NH; i += blockDim.x) {
        su[i] = us[i]; sd[i] = ud[i];
    }
    __syncthreads();
    int node = blockIdx.x * 8 + (threadIdx.x >> 5);
    if (node >= n) return;
    int lane = threadIdx.x & 31;
    float4 hv = *(const float4*)(hmat + (size_t)node * HID + lane * 4);
    float aS[NH], aD[NH];
#pragma unroll
    for (int hd = 0; hd < NH; hd++) {
        int b = (lane * 4) * NH + hd;
        aS[hd] = hv.x * su[b] + hv.y * su[b + NH] + hv.z * su[b + 2 * NH] + hv.w * su[b + 3 * NH];
        aD[hd] = hv.x * sd[b] + hv.y * sd[b + NH] + hv.z * sd[b + 2 * NH] + hv.w * sd[b + 3 * NH];
    }
#pragma unroll
    for (int off = 16; off > 0; off >>= 1) {
#pragma unroll
        for (int hd = 0; hd < NH; hd++) {
            aS[hd] += __shfl_xor_sync(0xffffffffu, aS[hd], off);
            aD[hd] += __shfl_xor_sync(0xffffffffu, aD[hd], off);
        }
    }
    if (lane < 8) {
        as_[(size_t)node * NH + lane] = aS[lane];
        ad_[(size_t)node * NH + lane] = aD[lane];
    }
}

// ------------------------- single-pass fused GAT edge kernel (2-deep pipeline) -------------------------
__device__ __forceinline__ float lrelu(float v) { return (v > 0.f) ? v : 0.2f * v; }

__global__ void gat_fused_kernel(const int* __restrict__ rowptr, const int* __restrict__ colsrc,
                                 const float* __restrict__ as_, const float* __restrict__ ad_,
                                 const float* __restrict__ hmat, float* __restrict__ agg, int n)
{
    int w = (blockIdx.x * blockDim.x + threadIdx.x) >> 5;
    int lane = threadIdx.x & 31;
    if (w >= n) return;
    const int dst = w;
    const int start = rowptr[dst];
    const int end   = rowptr[dst + 1];
    const int hh = lane & 7;

    const float advh = ad_[(size_t)dst * NH + hh];

    float4 acc[8];
#pragma unroll
    for (int h = 0; h < 8; h++) acc[h] = make_float4(0.f, 0.f, 0.f, 0.f);
    float den = 0.f;

    int   s_nx = colsrc[start];
    float c_nx = __expf(lrelu(as_[(size_t)s_nx * NH + hh] + advh));
    float4 h_nx = *(const float4*)(hmat + (size_t)s_nx * HID + lane * 4);

    for (int j = start; j < end; j++) {
        float4 hv = h_nx;
        float  cl = c_nx;
        if (j + 1 < end) {
            s_nx = colsrc[j + 1];
            c_nx = __expf(lrelu(as_[(size_t)s_nx * NH + hh] + advh));
            h_nx = *(const float4*)(hmat + (size_t)s_nx * HID + lane * 4);
        }
        den += cl;
#pragma unroll
        for (int h = 0; h < 8; h++) {
            float cc = __shfl_sync(0xffffffffu, cl, h);
            acc[h].x += cc * hv.x; acc[h].y += cc * hv.y;
            acc[h].z += cc * hv.z; acc[h].w += cc * hv.w;
        }
    }

    float invh = 0.125f / (den + 1e-16f);
    float* ap = agg + (size_t)dst * (NH * HID);
#pragma unroll
    for (int h = 0; h < 8; h++) {
        float iv = __shfl_sync(0xffffffffu, invh, h);
        float4 o = make_float4(rtf(acc[h].x * iv), rtf(acc[h].y * iv),
                               rtf(acc[h].z * iv), rtf(acc[h].w * iv));
        *(float4*)(ap + h * HID + lane * 4) = o;
    }
}

// ------------------------- fused GRU + pooling -------------------------
__global__ void gru_pool_kernel(const float* __restrict__ gi, const float* __restrict__ gh,
                                const float* __restrict__ mem, const int* __restrict__ batch,
                                float* __restrict__ sums, float* __restrict__ cnt, int n)
{
    int i = blockIdx.x * blockDim.x + threadIdx.x;
    if (i >= n * HID) return;
    int node = i >> 7, c = i & (HID - 1);
    size_t base = (size_t)node * (3 * HID);
    float gir = gi[base + c],           ghr = gh[base + c];
    float giz = gi[base + HID + c],     ghz = gh[base + HID + c];
    float gin = gi[base + 2 * HID + c], ghn = gh[base + 2 * HID + c];
    float r = 1.f / (1.f + expf(-(gir + ghr)));
    float z = 1.f / (1.f + expf(-(giz + ghz)));
    float nc = tanhf(gin + r * ghn);
    float mv = mem[i];
    float hn = (1.f - z) * nc + z * mv;
    int g = batch[node];
    atomicAdd(&sums[g * HID + c], hn);
    if (c == 0) atomicAdd(&cnt[g], 1.f);
}

__global__ void pooled_kernel(const float* __restrict__ sums, const float* __restrict__ cnt,
                              float* __restrict__ pooled, float* __restrict__ out_pooled)
{
    int i = blockIdx.x * blockDim.x + threadIdx.x;
    if (i >= NG * HID) return;
    int g = i >> 7;
    float v = sums[i] / fmaxf(cnt[g], 1.f);
    pooled[i] = v;
    out_pooled[i] = v;
}

__global__ void classifier_kernel(const float* __restrict__ pooled,
                                  const float* __restrict__ c1W, const float* __restrict__ c1b,
                                  const float* __restrict__ c2W, const float* __restrict__ c2b,
                                  float* __restrict__ out_logits, float* __restrict__ out_preds)
{
    int g = threadIdx.x;
    if (g >= NG) return;
    const float* p = pooled + g * HID;
    float lg[NCLS];
#pragma unroll
    for (int k = 0; k < NCLS; k++) lg[k] = c2b[k];
    for (int j = 0; j < HID / 2; j++) {
        float s = c1b[j];
        for (int c = 0; c < HID; c++) s += p[c] * c1W[c * (HID / 2) + j];
        s = fmaxf(s, 0.f);
#pragma unroll
        for (int k = 0; k < NCLS; k++) lg[k] += s * c2W[j * NCLS + k];
    }
    float m = fmaxf(lg[0], fmaxf(lg[1], lg[2]));
    float e0 = expf(lg[0] - m), e1 = expf(lg[1] - m), e2 = expf(lg[2] - m);
    float inv = 1.f / (e0 + e1 + e2);
#pragma unroll
    for (int k = 0; k < NCLS; k++) out_logits[g * NCLS + k] = lg[k];
    out_preds[g * NCLS + 0] = e0 * inv;
    out_preds[g * NCLS + 1] = e1 * inv;
    out_preds[g * NCLS + 2] = e2 * inv;
}

// ------------------------- launch -------------------------
extern "C" void kernel_launch(void* const* d_in, const int* in_sizes, int n_in,
                              void* d_out, int out_size)
{
    const float* x      = (const float*)d_in[0];
    const int*   ei     = (const int*)d_in[1];
    const int*   batch  = (const int*)d_in[2];
    const float* memory = (const float*)d_in[3];
    const float* enc_W  = (const float*)d_in[4];
    const float* enc_b  = (const float*)d_in[5];
    const float* gat_W  = (const float*)d_in[6];
    const float* att_s  = (const float*)d_in[7];
    const float* att_d  = (const float*)d_in[8];
    const float* gat_b  = (const float*)d_in[9];
    const float* W_ih   = (const float*)d_in[10];
    const float* W_hh   = (const float*)d_in[11];
    const float* b_ih   = (const float*)d_in[12];
    const float* b_hh   = (const float*)d_in[13];
    const float* c1W    = (const float*)d_in[14];
    const float* c1b    = (const float*)d_in[15];
    const float* c2W    = (const float*)d_in[16];
    const float* c2b    = (const float*)d_in[17];
    float* out = (float*)d_out;

    const int n    = in_sizes[2];
    const int E    = in_sizes[1] / 2;
    const int Etot = E + n;
    const int F    = in_sizes[0] / n;

    float *h, *agg, *as_, *ad_, *gi, *gh, *sums, *cnt, *pooled, *us, *ud, *wst;
    float *xr, *memr, *encwr, *wihr, *whhr;
    int *deg, *rowptr, *cursor, *colsrc;
    cudaGetSymbolAddress((void**)&h, g_h);
    cudaGetSymbolAddress((void**)&agg, g_agg);
    cudaGetSymbolAddress((void**)&as_, g_as);
    cudaGetSymbolAddress((void**)&ad_, g_ad);
    cudaGetSymbolAddress((void**)&gi, g_gi);
    cudaGetSymbolAddress((void**)&gh, g_gh);
    cudaGetSymbolAddress((void**)&sums, g_sums);
    cudaGetSymbolAddress((void**)&cnt, g_cnt);
    cudaGetSymbolAddress((void**)&pooled, g_pool);
    cudaGetSymbolAddress((void**)&us, g_us);
    cudaGetSymbolAddress((void**)&ud, g_ud);
    cudaGetSymbolAddress((void**)&wst, g_wst);
    cudaGetSymbolAddress((void**)&xr, g_xr);
    cudaGetSymbolAddress((void**)&memr, g_memr);
    cudaGetSymbolAddress((void**)&encwr, g_encwr);
    cudaGetSymbolAddress((void**)&wihr, g_wihr);
    cudaGetSymbolAddress((void**)&whhr, g_whhr);
    cudaGetSymbolAddress((void**)&deg, g_deg);
    cudaGetSymbolAddress((void**)&rowptr, g_rowptr);
    cudaGetSymbolAddress((void**)&cursor, g_cursor);
    cudaGetSymbolAddress((void**)&colsrc, g_colsrc);

    // opt-in to >48KB dynamic smem for the GEMM kernels (host-side, capture-safe)
    cudaFuncSetAttribute((const void*)tf32gemm<false>,
                         cudaFuncAttributeMaxDynamicSharedMemorySize, SMEM_GEMM);
    cudaFuncSetAttribute((const void*)tf32gemm<true>,
                         cudaFuncAttributeMaxDynamicSharedMemorySize, SMEM_GEMM);
    cudaFuncSetAttribute((const void*)tf32gemm_dual,
                         cudaFuncAttributeMaxDynamicSharedMemorySize, SMEM_GEMM);

    const int T = 256;

    // ---- build CSR (dst-sorted) once ----
    zero_kernel<<<(n + T - 1) / T, T>>>((unsigned*)deg, n);
    hist_kernel<<<(Etot + T - 1) / T, T>>>(ei, deg, E, n);
    scan_kernel<<<1, 1024>>>(deg, rowptr, cursor, n);
    scatter_kernel<<<(Etot + T - 1) / T, T>>>(ei, cursor, colsrc, E, n);

    // ---- zero pool accumulators early ----
    zero_kernel<<<(NG * HID + T - 1) / T, T>>>((unsigned*)sums, NG * HID);
    zero_kernel<<<1, NG>>>((unsigned*)cnt, NG);

    // ---- tf32 pre-rounding of all mma operands ----
    {
        dim3 g2((unsigned)(((size_t)n * HID + T - 1) / T), 2);
        round_copy2_kernel<<<g2, T>>>(x, xr, memory, memr, (size_t)n * HID);
    }
    {
        dim3 g2((3 * HID * HID + T - 1) / T, 2);
        round_copy2_kernel<<<g2, T>>>(W_ih, wihr, W_hh, whhr, 3 * HID * HID);
    }
    round_copy_kernel<<<(HID * HID + T - 1) / T, T>>>(enc_W, encwr, HID * HID);

    stackW_kernel<<<dim3((NH * HID * HID + T - 1) / T, NLAY), T>>>(gat_W, wst);
    fold_att_kernel<<<dim3(NH, NLAY), HID>>>(gat_W, att_s, att_d, us, ud);

    const int MB = (n + 127) / 128;

    // ---- encoder ----
    tf32gemm<false><<<dim3(1, MB), T, SMEM_GEMM>>>(xr, encwr, enc_b, h, n, HID, F, 1, 0);

    // ---- GAT layers ----
    for (int l = 0; l < NLAY; l++) {
        alpha2_kernel<<<(n + 7) / 8, T>>>(h, us + (size_t)l * HID * NH,
                                          ud + (size_t)l * HID * NH, as_, ad_, n);
        gat_fused_kernel<<<(int)(((size_t)n * 32 + T - 1) / T), T>>>(
            rowptr, colsrc, as_, ad_, h, agg, n);
        tf32gemm<false><<<dim3(1, MB), T, SMEM_GEMM>>>(
            agg, wst + (size_t)l * NH * HID * HID, gat_b + (size_t)l * HID, h,
            n, HID, NH * HID, (l < NLAY - 1) ? 1 : 0, (l == NLAY - 1) ? 1 : 0);
    }

    // ---- GRU (both projections in one launch) ----
    tf32gemm_dual<<<dim3(3 * HID / 128, MB, 2), T, SMEM_GEMM>>>(
        h, wihr, b_ih, gi, memr, whhr, b_hh, gh, n, 3 * HID, HID);
    gru_pool_kernel<<<(int)(((size_t)n * HID + T - 1) / T), T>>>(
        gi, gh, memr, batch, sums, cnt, n);

    // ---- pooled + classifier ----
    float* out_logits = out;
    float* out_pooled = out + NG * NCLS;
    float* out_preds  = out + NG * NCLS + NG * HID;
    pooled_kernel<<<(NG * HID + T - 1) / T, T>>>(sums, cnt, pooled, out_pooled);
    classifier_kernel<<<1, NG>>>(pooled, c1W, c1b, c2W, c2b, out_logits, out_preds);
}